// round 1
// baseline (speedup 1.0000x reference)
#include <cuda_runtime.h>

// Problem constants
#define NB    8
#define NP    2048
#define BN    (NB * NP)
#define ITERS 50

// eps = 0.005
//   SF     = 1/(eps*ln2)           (log2-domain scale)
//   TWOSF  = 2*SF                  (for 2*s*p.q)
//   EPSLN2 = eps*ln2 = 1/SF
//   LOG2NF = log2(N) = 11
#define SF      288.5390081777927f
#define TWOSF   577.0780163555854f
#define EPSLN2  0.0034657359027997264f
#define LOG2NF  11.0f

// Scratch (static device arrays: no allocation in kernel_launch)
// p{1,2}r : (x, y, z, |p|^2)        -- j-side (raw) view
// p{1,2}s : (2s*x, 2s*y, 2s*z, |p|^2) -- i-side (scaled) view
// h1 = s*(f - |p1|^2), h2 = s*(g - |p2|^2)  (log2-domain potentials)
__device__ float4 g_p1r[BN], g_p1s[BN], g_p2r[BN], g_p2s[BN];
__device__ float  g_h1[BN], g_h2[BN];
__device__ float  g_part[BN / 32];

__device__ __forceinline__ float ex2f(float x) {
    float r; asm("ex2.approx.ftz.f32 %0, %1;" : "=f"(r) : "f"(x)); return r;
}
__device__ __forceinline__ float lg2f(float x) {
    float r; asm("lg2.approx.ftz.f32 %0, %1;" : "=f"(r) : "f"(x)); return r;
}

// ---------------------------------------------------------------------------
// Init: build SoA/float4 views + initial potentials (f = g = 0 -> h = -s*|p|^2)
// ---------------------------------------------------------------------------
__global__ void init_k(const float* __restrict__ pc1, const float* __restrict__ pc2) {
    int idx = blockIdx.x * blockDim.x + threadIdx.x;
    if (idx >= BN) return;

    float x = pc1[3 * idx + 0], y = pc1[3 * idx + 1], z = pc1[3 * idx + 2];
    float sq = x * x + y * y + z * z;
    g_p1r[idx] = make_float4(x, y, z, sq);
    g_p1s[idx] = make_float4(TWOSF * x, TWOSF * y, TWOSF * z, sq);
    g_h1[idx]  = -SF * sq;

    x = pc2[3 * idx + 0]; y = pc2[3 * idx + 1]; z = pc2[3 * idx + 2];
    sq = x * x + y * y + z * z;
    g_p2r[idx] = make_float4(x, y, z, sq);
    g_p2s[idx] = make_float4(TWOSF * x, TWOSF * y, TWOSF * z, sq);
    g_h2[idx]  = -SF * sq;
}

// ---------------------------------------------------------------------------
// One Sinkhorn half-step in log2 domain.
//   dir=0: f-update  (rows = set1, reduce over set2, writes h1)
//   dir=1: g-update  (rows = set2, reduce over set1, writes h2)
// A_j = h_j + (2s p_i).q_j  ;  h_out_i = -log2(N) - LSE2_j(A_j)
// One warp per 32 rows (lane = row); j-side loads are warp-uniform broadcasts.
// ---------------------------------------------------------------------------
__global__ void __launch_bounds__(32) upd_k(int dir) {
    const float4* __restrict__ pis = dir ? g_p2s : g_p1s;
    const float4* __restrict__ pjr = dir ? g_p1r : g_p2r;
    const float*  __restrict__ hj  = dir ? g_h1  : g_h2;
    float*        __restrict__ ho  = dir ? g_h2  : g_h1;

    int lane = threadIdx.x;
    int gw   = blockIdx.x;            // 0 .. BN/32-1
    int b    = gw >> 6;               // NP/32 = 64 warps per batch
    int i    = ((gw & 63) << 5) + lane;
    int base = b * NP;

    float4 p  = __ldg(pis + base + i);
    float  cx = p.x, cy = p.y, cz = p.z;

    const float4* q = pjr + base;
    const float*  h = hj  + base;

    float m  = -1e30f;
    float s0 = 0.f, s1 = 0.f, s2 = 0.f, s3 = 0.f;

    #pragma unroll 1
    for (int j = 0; j < NP; j += 8) {
        float A[8];
        #pragma unroll
        for (int k = 0; k < 8; k++) {
            float4 qq = __ldg(q + j + k);
            float  hv = __ldg(h + j + k);
            A[k] = fmaf(cx, qq.x, fmaf(cy, qq.y, fmaf(cz, qq.z, hv)));
        }
        float m01 = fmaxf(A[0], A[1]);
        float m23 = fmaxf(A[2], A[3]);
        float m45 = fmaxf(A[4], A[5]);
        float m67 = fmaxf(A[6], A[7]);
        float cmax = fmaxf(fmaxf(m01, m23), fmaxf(m45, m67));

        if (cmax > m) {           // rare after the running max stabilizes
            float sc = ex2f(m - cmax);
            s0 *= sc; s1 *= sc; s2 *= sc; s3 *= sc;
            m = cmax;
        }
        s0 += ex2f(A[0] - m);
        s1 += ex2f(A[1] - m);
        s2 += ex2f(A[2] - m);
        s3 += ex2f(A[3] - m);
        s0 += ex2f(A[4] - m);
        s1 += ex2f(A[5] - m);
        s2 += ex2f(A[6] - m);
        s3 += ex2f(A[7] - m);
    }

    float ss = (s0 + s1) + (s2 + s3);
    ho[base + i] = -LOG2NF - m - lg2f(ss);
}

// ---------------------------------------------------------------------------
// Final pass: dist_i = N * sum_j exp((f_i+g_j-C_ij)/eps) * C_ij, then
// per-warp partial sum of sqrt(dist + 1e-12).
//   exponent2 = h1_i + A_j (all terms <= log2(1/N) < 0 at convergence)
//   C_ij      = |p_i|^2 + |q_j|^2 - (A_j - h2_j)*eps*ln2
// ---------------------------------------------------------------------------
__global__ void __launch_bounds__(32) dist_k() {
    int lane = threadIdx.x;
    int gw   = blockIdx.x;
    int b    = gw >> 6;
    int i    = ((gw & 63) << 5) + lane;
    int base = b * NP;

    float4 p   = __ldg(g_p1s + base + i);
    float  cx  = p.x, cy = p.y, cz = p.z, sq1 = p.w;
    float  tf  = __ldg(g_h1 + base + i);

    const float4* q = g_p2r + base;
    const float*  h = g_h2  + base;

    float a0 = 0.f, a1 = 0.f, a2 = 0.f, a3 = 0.f;

    #pragma unroll 1
    for (int j = 0; j < NP; j += 4) {
        #pragma unroll
        for (int k = 0; k < 4; k++) {
            float4 qq = __ldg(q + j + k);
            float  hv = __ldg(h + j + k);
            float  A  = fmaf(cx, qq.x, fmaf(cy, qq.y, fmaf(cz, qq.z, hv)));
            float  e  = ex2f(tf + A);
            float  C  = sq1 + qq.w - (A - hv) * EPSLN2;
            float  pc = e * C;
            if (k == 0) a0 += pc;
            else if (k == 1) a1 += pc;
            else if (k == 2) a2 += pc;
            else a3 += pc;
        }
    }

    float acc = (a0 + a1) + (a2 + a3);
    float v = sqrtf((float)NP * acc + 1e-12f);
    #pragma unroll
    for (int o = 16; o; o >>= 1) v += __shfl_xor_sync(0xffffffffu, v, o);
    if (lane == 0) g_part[gw] = v;
}

// ---------------------------------------------------------------------------
// Deterministic final reduction of the 512 per-warp partials -> mean
// ---------------------------------------------------------------------------
__global__ void finish_k(float* __restrict__ out) {
    __shared__ float sh[BN / 32];
    int t = threadIdx.x;
    sh[t] = g_part[t];
    __syncthreads();
    for (int s = (BN / 32) / 2; s > 0; s >>= 1) {
        if (t < s) sh[t] += sh[t + s];
        __syncthreads();
    }
    if (t == 0) out[0] = sh[0] * (1.0f / (float)BN);
}

// ---------------------------------------------------------------------------
extern "C" void kernel_launch(void* const* d_in, const int* in_sizes, int n_in,
                              void* d_out, int out_size) {
    const float* pc1 = (const float*)d_in[0];
    const float* pc2 = (const float*)d_in[1];
    float* out = (float*)d_out;

    init_k<<<(BN + 255) / 256, 256>>>(pc1, pc2);

    for (int it = 0; it < ITERS; it++) {
        upd_k<<<BN / 32, 32>>>(0);   // f-update (uses g via h2, writes h1)
        upd_k<<<BN / 32, 32>>>(1);   // g-update (uses new f via h1, writes h2)
    }

    dist_k<<<BN / 32, 32>>>();
    finish_k<<<1, BN / 32>>>(out);

    (void)in_sizes; (void)n_in; (void)out_size;
}

// round 2
// speedup vs baseline: 2.9953x; 2.9953x over previous
#include <cuda_runtime.h>

// Problem constants
#define NB    8
#define NP    2048
#define BN    (NB * NP)
#define ITERS 50
#define NWARP 8                  // j-split warps per 32-row group
#define JCH   (NP / NWARP)       // 256 j's per warp

// eps = 0.005
#define SF      288.5390081777927f    // 1/(eps*ln2)
#define TWOSF   577.0780163555854f    // 2/(eps*ln2)
#define EPSLN2  0.0034657359027997264f
#define LOG2NF  11.0f

// raw{1,2}: (x, y, z, |p|^2)           -- i-side in upd, both sides in dist
// pk{1,2} : (2s*x, 2s*y, 2s*z, h)      -- j-side packed coords + potential
//           h1 = s*(f - |p1|^2), h2 = s*(g - |p2|^2), s = 1/(eps ln2)
__device__ float4 g_raw1[BN], g_raw2[BN], g_pk1[BN], g_pk2[BN];
__device__ float  g_part[BN / 32];

__device__ __forceinline__ float ex2f(float x) {
    float r; asm("ex2.approx.ftz.f32 %0, %1;" : "=f"(r) : "f"(x)); return r;
}
__device__ __forceinline__ float lg2f(float x) {
    float r; asm("lg2.approx.ftz.f32 %0, %1;" : "=f"(r) : "f"(x)); return r;
}

// ---------------------------------------------------------------------------
__global__ void init_k(const float* __restrict__ pc1, const float* __restrict__ pc2) {
    int idx = blockIdx.x * blockDim.x + threadIdx.x;
    if (idx >= BN) return;

    float x = pc1[3 * idx + 0], y = pc1[3 * idx + 1], z = pc1[3 * idx + 2];
    float sq = x * x + y * y + z * z;
    g_raw1[idx] = make_float4(x, y, z, sq);
    g_pk1[idx]  = make_float4(TWOSF * x, TWOSF * y, TWOSF * z, -SF * sq);

    x = pc2[3 * idx + 0]; y = pc2[3 * idx + 1]; z = pc2[3 * idx + 2];
    sq = x * x + y * y + z * z;
    g_raw2[idx] = make_float4(x, y, z, sq);
    g_pk2[idx]  = make_float4(TWOSF * x, TWOSF * y, TWOSF * z, -SF * sq);
}

// ---------------------------------------------------------------------------
// One Sinkhorn half-step, log2 domain.
//   A_j = p_i . (2s q_j) + h_j   (q packed as (2s x, 2s y, 2s z, h))
//   h_out_i = -log2(N) - LSE2_j(A_j)
// Block = 8 warps x 32 lanes. lane = row (32 rows per block); each warp
// covers a 256-j chunk with streaming LSE; log-domain merge in smem.
//   dir=0: rows=set1 (raw1), j=set2 (pk2), writes pk1.w
//   dir=1: rows=set2 (raw2), j=set1 (pk1), writes pk2.w
// ---------------------------------------------------------------------------
__global__ void __launch_bounds__(32 * NWARP) upd_k(int dir) {
    const float4* __restrict__ ri = dir ? g_raw2 : g_raw1;
    const float4* __restrict__ pj = dir ? g_pk1  : g_pk2;
    float4*       __restrict__ po = dir ? g_pk2  : g_pk1;

    int lane = threadIdx.x & 31;
    int w    = threadIdx.x >> 5;            // 0..NWARP-1 : j-chunk
    int blk  = blockIdx.x;                  // 0..511
    int b    = blk >> 6;                    // 64 row-blocks per batch
    int i    = ((blk & 63) << 5) + lane;
    int base = b * NP;

    float4 p  = __ldg(ri + base + i);
    const float4* q = pj + base + w * JCH;

    float m  = -1e30f;
    float s0 = 0.f, s1 = 0.f, s2 = 0.f, s3 = 0.f;

    #pragma unroll 1
    for (int j = 0; j < JCH; j += 8) {
        float A[8];
        #pragma unroll
        for (int k = 0; k < 8; k++) {
            float4 qq = __ldg(q + j + k);
            A[k] = fmaf(p.x, qq.x, fmaf(p.y, qq.y, fmaf(p.z, qq.z, qq.w)));
        }
        float m01 = fmaxf(A[0], A[1]);
        float m23 = fmaxf(A[2], A[3]);
        float m45 = fmaxf(A[4], A[5]);
        float m67 = fmaxf(A[6], A[7]);
        float cmax = fmaxf(fmaxf(m01, m23), fmaxf(m45, m67));

        if (cmax > m) {                      // rare once running max settles
            float sc = ex2f(m - cmax);
            s0 *= sc; s1 *= sc; s2 *= sc; s3 *= sc;
            m = cmax;
        }
        s0 += ex2f(A[0] - m);
        s1 += ex2f(A[1] - m);
        s2 += ex2f(A[2] - m);
        s3 += ex2f(A[3] - m);
        s0 += ex2f(A[4] - m);
        s1 += ex2f(A[5] - m);
        s2 += ex2f(A[6] - m);
        s3 += ex2f(A[7] - m);
    }
    float s = (s0 + s1) + (s2 + s3);

    __shared__ float msh[NWARP][32];
    __shared__ float ssh[NWARP][32];
    msh[w][lane] = m;
    ssh[w][lane] = s;
    __syncthreads();

    if (w == 0) {
        float M = msh[0][lane];
        #pragma unroll
        for (int k = 1; k < NWARP; k++) M = fmaxf(M, msh[k][lane]);
        float S = 0.f;
        #pragma unroll
        for (int k = 0; k < NWARP; k++) S += ssh[k][lane] * ex2f(msh[k][lane] - M);
        ((float*)(po + base + i))[3] = -LOG2NF - M - lg2f(S);
    }
}

// ---------------------------------------------------------------------------
// dist_i = N * sum_j exp2(h1_i + A_j) * C_ij ; C = sq1 + sq2 - (A - h2)*eps*ln2
// Same 8-warp j-split; plain sum merge (exponents <= ~-log2 N, no overflow).
// ---------------------------------------------------------------------------
__global__ void __launch_bounds__(32 * NWARP) dist_k() {
    int lane = threadIdx.x & 31;
    int w    = threadIdx.x >> 5;
    int blk  = blockIdx.x;
    int b    = blk >> 6;
    int i    = ((blk & 63) << 5) + lane;
    int base = b * NP;

    float4 p  = __ldg(g_raw1 + base + i);       // (x,y,z,sq1)
    float  tf = __ldg((const float*)(g_pk1 + base + i) + 3);  // h1_i

    const float4* q = g_pk2  + base + w * JCH;  // (2s x, 2s y, 2s z, h2)
    const float4* r = g_raw2 + base + w * JCH;  // .w = sq2

    float a0 = 0.f, a1 = 0.f, a2 = 0.f, a3 = 0.f;

    #pragma unroll 1
    for (int j = 0; j < JCH; j += 4) {
        #pragma unroll
        for (int k = 0; k < 4; k++) {
            float4 qq = __ldg(q + j + k);
            float  sq2 = __ldg((const float*)(r + j + k) + 3);
            float  A  = fmaf(p.x, qq.x, fmaf(p.y, qq.y, fmaf(p.z, qq.z, qq.w)));
            float  e  = ex2f(tf + A);
            float  C  = p.w + sq2 - (A - qq.w) * EPSLN2;
            float  pc = e * C;
            if      (k == 0) a0 += pc;
            else if (k == 1) a1 += pc;
            else if (k == 2) a2 += pc;
            else             a3 += pc;
        }
    }
    float acc = (a0 + a1) + (a2 + a3);

    __shared__ float ash[NWARP][32];
    ash[w][lane] = acc;
    __syncthreads();

    if (w == 0) {
        float S = ash[0][lane];
        #pragma unroll
        for (int k = 1; k < NWARP; k++) S += ash[k][lane];
        float v = sqrtf((float)NP * S + 1e-12f);
        #pragma unroll
        for (int o = 16; o; o >>= 1) v += __shfl_xor_sync(0xffffffffu, v, o);
        if (lane == 0) g_part[blk] = v;
    }
}

// ---------------------------------------------------------------------------
__global__ void finish_k(float* __restrict__ out) {
    __shared__ float sh[BN / 32];
    int t = threadIdx.x;
    sh[t] = g_part[t];
    __syncthreads();
    for (int s = (BN / 32) / 2; s > 0; s >>= 1) {
        if (t < s) sh[t] += sh[t + s];
        __syncthreads();
    }
    if (t == 0) out[0] = sh[0] * (1.0f / (float)BN);
}

// ---------------------------------------------------------------------------
extern "C" void kernel_launch(void* const* d_in, const int* in_sizes, int n_in,
                              void* d_out, int out_size) {
    const float* pc1 = (const float*)d_in[0];
    const float* pc2 = (const float*)d_in[1];
    float* out = (float*)d_out;

    init_k<<<(BN + 255) / 256, 256>>>(pc1, pc2);

    for (int it = 0; it < ITERS; it++) {
        upd_k<<<BN / 32, 32 * NWARP>>>(0);   // f-update: reads pk2, writes pk1.w
        upd_k<<<BN / 32, 32 * NWARP>>>(1);   // g-update: reads pk1, writes pk2.w
    }

    dist_k<<<BN / 32, 32 * NWARP>>>();
    finish_k<<<1, BN / 32>>>(out);

    (void)in_sizes; (void)n_in; (void)out_size;
}

// round 3
// speedup vs baseline: 4.7077x; 1.5717x over previous
#include <cuda_runtime.h>

// Problem constants
#define NB    8
#define NP    2048
#define BN    (NB * NP)
#define ITERS 50
#define NWARP 8                  // j-split warps per 32-row group
#define JCH   (NP / NWARP)       // 256 j's per warp

// eps = 0.005
#define SF      288.5390081777927f    // 1/(eps*ln2)
#define TWOSF   577.0780163555854f    // 2/(eps*ln2)
#define EPSLN2  0.0034657359027997264f
#define LOG2NF  11.0f

// raw{1,2}: (x, y, z, |p|^2)           -- i-side in upd, both sides in dist
// pk{1,2} : (2s*x, 2s*y, 2s*z, h)      -- j-side packed coords + potential
//           h1 = s*(f - |p1|^2), h2 = s*(g - |p2|^2), s = 1/(eps ln2)
__device__ float4 g_raw1[BN], g_raw2[BN], g_pk1[BN], g_pk2[BN];
__device__ float  g_part[BN / 32];

__device__ __forceinline__ float ex2f(float x) {
    float r; asm("ex2.approx.ftz.f32 %0, %1;" : "=f"(r) : "f"(x)); return r;
}
__device__ __forceinline__ float lg2f(float x) {
    float r; asm("lg2.approx.ftz.f32 %0, %1;" : "=f"(r) : "f"(x)); return r;
}

// ---------------------------------------------------------------------------
__global__ void init_k(const float* __restrict__ pc1, const float* __restrict__ pc2) {
    int idx = blockIdx.x * blockDim.x + threadIdx.x;
    if (idx >= BN) return;

    float x = pc1[3 * idx + 0], y = pc1[3 * idx + 1], z = pc1[3 * idx + 2];
    float sq = x * x + y * y + z * z;
    g_raw1[idx] = make_float4(x, y, z, sq);
    g_pk1[idx]  = make_float4(TWOSF * x, TWOSF * y, TWOSF * z, -SF * sq);

    x = pc2[3 * idx + 0]; y = pc2[3 * idx + 1]; z = pc2[3 * idx + 2];
    sq = x * x + y * y + z * z;
    g_raw2[idx] = make_float4(x, y, z, sq);
    g_pk2[idx]  = make_float4(TWOSF * x, TWOSF * y, TWOSF * z, -SF * sq);
}

// ---------------------------------------------------------------------------
// One Sinkhorn half-step, log2 domain.
//   A_j = p_i . (2s q_j) + h_j ;  h_out_i = -log2(N) - LSE2_j(A_j)
// Block = 8 warps x 32 lanes; lane = row. The whole 2048-point j-side is
// staged into smem once per block (coalesced LDG), then the inner loop is
// warp-uniform LDS.128 broadcasts -- L1tex stays idle, smem crossbar
// broadcast is conflict-free.
// ---------------------------------------------------------------------------
__global__ void __launch_bounds__(32 * NWARP, 4) upd_k(int dir) {
    const float4* __restrict__ ri = dir ? g_raw2 : g_raw1;
    const float4* __restrict__ pj = dir ? g_pk1  : g_pk2;
    float4*       __restrict__ po = dir ? g_pk2  : g_pk1;

    __shared__ float4 sj[NP];                 // 32 KB j-side tile
    __shared__ float  msh[NWARP][32];
    __shared__ float  ssh[NWARP][32];

    int lane = threadIdx.x & 31;
    int w    = threadIdx.x >> 5;              // 0..NWARP-1 : j-chunk
    int blk  = blockIdx.x;                    // 0..511
    int b    = blk >> 6;                      // 64 row-blocks per batch
    int i    = ((blk & 63) << 5) + lane;
    int base = b * NP;

    // Stage the full j-side for this batch (coalesced, once per launch)
    #pragma unroll
    for (int t = 0; t < NP / (32 * NWARP); t++)
        sj[t * 32 * NWARP + threadIdx.x] = __ldg(pj + base + t * 32 * NWARP + threadIdx.x);

    float4 p = __ldg(ri + base + i);
    __syncthreads();

    const float4* q = sj + w * JCH;

    float m  = -1e30f;
    float s0 = 0.f, s1 = 0.f, s2 = 0.f, s3 = 0.f;

    #pragma unroll 1
    for (int j = 0; j < JCH; j += 8) {
        float A[8];
        #pragma unroll
        for (int k = 0; k < 8; k++) {
            float4 qq = q[j + k];             // LDS.128, warp-uniform broadcast
            A[k] = fmaf(p.x, qq.x, fmaf(p.y, qq.y, fmaf(p.z, qq.z, qq.w)));
        }
        float m01 = fmaxf(A[0], A[1]);
        float m23 = fmaxf(A[2], A[3]);
        float m45 = fmaxf(A[4], A[5]);
        float m67 = fmaxf(A[6], A[7]);
        float cmax = fmaxf(fmaxf(m01, m23), fmaxf(m45, m67));

        if (cmax > m) {                       // rare once running max settles
            float sc = ex2f(m - cmax);
            s0 *= sc; s1 *= sc; s2 *= sc; s3 *= sc;
            m = cmax;
        }
        s0 += ex2f(A[0] - m);
        s1 += ex2f(A[1] - m);
        s2 += ex2f(A[2] - m);
        s3 += ex2f(A[3] - m);
        s0 += ex2f(A[4] - m);
        s1 += ex2f(A[5] - m);
        s2 += ex2f(A[6] - m);
        s3 += ex2f(A[7] - m);
    }
    float s = (s0 + s1) + (s2 + s3);

    msh[w][lane] = m;
    ssh[w][lane] = s;
    __syncthreads();

    if (w == 0) {
        float M = msh[0][lane];
        #pragma unroll
        for (int k = 1; k < NWARP; k++) M = fmaxf(M, msh[k][lane]);
        float S = 0.f;
        #pragma unroll
        for (int k = 0; k < NWARP; k++) S += ssh[k][lane] * ex2f(msh[k][lane] - M);
        ((float*)(po + base + i))[3] = -LOG2NF - M - lg2f(S);
    }
}

// ---------------------------------------------------------------------------
// dist_i = N * sum_j exp2(h1_i + A_j) * C_ij ; C = sq1 + sq2 - (A - h2)*eps*ln2
// Same smem staging (pk2 + sq2), plain sum merge.
// ---------------------------------------------------------------------------
__global__ void __launch_bounds__(32 * NWARP, 4) dist_k() {
    __shared__ float4 sj[NP];                 // (2s x, 2s y, 2s z, h2)
    __shared__ float  ssq[NP];                // |q|^2
    __shared__ float  ash[NWARP][32];

    int lane = threadIdx.x & 31;
    int w    = threadIdx.x >> 5;
    int blk  = blockIdx.x;
    int b    = blk >> 6;
    int i    = ((blk & 63) << 5) + lane;
    int base = b * NP;

    #pragma unroll
    for (int t = 0; t < NP / (32 * NWARP); t++) {
        int idx = t * 32 * NWARP + threadIdx.x;
        sj[idx]  = __ldg(g_pk2 + base + idx);
        ssq[idx] = __ldg((const float*)(g_raw2 + base + idx) + 3);
    }

    float4 p  = __ldg(g_raw1 + base + i);     // (x,y,z,sq1)
    float  tf = __ldg((const float*)(g_pk1 + base + i) + 3);  // h1_i
    __syncthreads();

    const float4* q  = sj  + w * JCH;
    const float*  r2 = ssq + w * JCH;

    float a0 = 0.f, a1 = 0.f, a2 = 0.f, a3 = 0.f;

    #pragma unroll 1
    for (int j = 0; j < JCH; j += 4) {
        #pragma unroll
        for (int k = 0; k < 4; k++) {
            float4 qq  = q[j + k];
            float  sq2 = r2[j + k];
            float  A   = fmaf(p.x, qq.x, fmaf(p.y, qq.y, fmaf(p.z, qq.z, qq.w)));
            float  e   = ex2f(tf + A);
            float  C   = p.w + sq2 - (A - qq.w) * EPSLN2;
            float  pc  = e * C;
            if      (k == 0) a0 += pc;
            else if (k == 1) a1 += pc;
            else if (k == 2) a2 += pc;
            else             a3 += pc;
        }
    }
    float acc = (a0 + a1) + (a2 + a3);

    ash[w][lane] = acc;
    __syncthreads();

    if (w == 0) {
        float S = ash[0][lane];
        #pragma unroll
        for (int k = 1; k < NWARP; k++) S += ash[k][lane];
        float v = sqrtf((float)NP * S + 1e-12f);
        #pragma unroll
        for (int o = 16; o; o >>= 1) v += __shfl_xor_sync(0xffffffffu, v, o);
        if (lane == 0) g_part[blk] = v;
    }
}

// ---------------------------------------------------------------------------
__global__ void finish_k(float* __restrict__ out) {
    __shared__ float sh[BN / 32];
    int t = threadIdx.x;
    sh[t] = g_part[t];
    __syncthreads();
    for (int s = (BN / 32) / 2; s > 0; s >>= 1) {
        if (t < s) sh[t] += sh[t + s];
        __syncthreads();
    }
    if (t == 0) out[0] = sh[0] * (1.0f / (float)BN);
}

// ---------------------------------------------------------------------------
extern "C" void kernel_launch(void* const* d_in, const int* in_sizes, int n_in,
                              void* d_out, int out_size) {
    const float* pc1 = (const float*)d_in[0];
    const float* pc2 = (const float*)d_in[1];
    float* out = (float*)d_out;

    init_k<<<(BN + 255) / 256, 256>>>(pc1, pc2);

    for (int it = 0; it < ITERS; it++) {
        upd_k<<<BN / 32, 32 * NWARP>>>(0);   // f-update: reads pk2, writes pk1.w
        upd_k<<<BN / 32, 32 * NWARP>>>(1);   // g-update: reads pk1, writes pk2.w
    }

    dist_k<<<BN / 32, 32 * NWARP>>>();
    finish_k<<<1, BN / 32>>>(out);

    (void)in_sizes; (void)n_in; (void)out_size;
}